// round 13
// baseline (speedup 1.0000x reference)
#include <cuda_runtime.h>
#include <cuda_bf16.h>
#include <cstdint>

// Problem constants: N=100000, E=1600000, D=64, L=3
#define NODES_MAX 100000
#define EDGES_MAX 1600000
#define FEATS     64
#define SCAN_BLK  512
#define SCAN_NBLK ((NODES_MAX + 1 + SCAN_BLK - 1) / SCAN_BLK)   // 196

// Scratch (device globals: runtime allocation forbidden)
__device__ __align__(16) float g_agg [NODES_MAX * FEATS];
__device__ __align__(16) float g_buf0[NODES_MAX * FEATS];
__device__ __align__(16) float g_buf1[NODES_MAX * FEATS];
__device__ __align__(16) float g_WlT [3 * FEATS * FEATS];   // transposed [k][j]
__device__ __align__(16) float g_WrT [3 * FEATS * FEATS];   // transposed [k][j]
__device__ int g_deg     [NODES_MAX];
__device__ int g_rowstart[NODES_MAX + 1];
__device__ int g_cursor  [NODES_MAX];
__device__ int g_csr     [EDGES_MAX];
__device__ int g_blocksum[SCAN_NBLK];
__device__ int g_ei64;   // 1 = edge_index is int64, 0 = int32

// ---------------------------------------------------------------------------
// Fused one-time setup: zero deg, transpose weights, detect edge-index dtype.
// (int64 values < 2^31 => every odd 32-bit word of the buffer is zero.)
__global__ void setup_kernel(const unsigned int* __restrict__ eiw,
                             const float* __restrict__ Wl,
                             const float* __restrict__ Wr,
                             float* __restrict__ WlT,
                             float* __restrict__ WrT,
                             int* __restrict__ deg, int n) {
    int i = blockIdx.x * blockDim.x + threadIdx.x;
    if (i < n) deg[i] = 0;
    if (i < 3 * FEATS * FEATS) {
        int layer = i >> 12, r = i & 4095;
        int j = r >> 6, k = r & 63;
        WlT[(layer << 12) + (k << 6) + j] = Wl[i];
        WrT[(layer << 12) + (k << 6) + j] = Wr[i];
    }
    if (blockIdx.x == 0) {
        __shared__ unsigned int rr;
        if (threadIdx.x == 0) rr = 0u;
        __syncthreads();
        unsigned int v = eiw[2 * threadIdx.x + 1];   // 256 odd words
        atomicOr(&rr, v);
        __syncthreads();
        if (threadIdx.x == 0) g_ei64 = (rr == 0u) ? 1 : 0;
    }
}

// ---------------------------------------------------------------------------
// in-degree histogram — 2 edges per thread, 16B index loads
__global__ void hist_kernel(const void* __restrict__ ei, int* __restrict__ deg,
                            int E, int n) {
    int t = blockIdx.x * blockDim.x + threadIdx.x;
    int e = t * 2;
    if (e >= E) return;
    long long d0, d1;
    if (g_ei64) {
        longlong2 v = *(const longlong2*)((const long long*)ei + E + e);
        d0 = v.x; d1 = v.y;
    } else {
        int2 v = *(const int2*)((const int*)ei + E + e);
        d0 = v.x; d1 = v.y;
    }
    if ((unsigned long long)d0 < (unsigned long long)n) atomicAdd(deg + d0, 1);
    if (e + 1 < E && (unsigned long long)d1 < (unsigned long long)n) atomicAdd(deg + d1, 1);
}

// ---------------------------------------------------------------------------
// Chip-wide exclusive scan, 3 kernels.
__global__ __launch_bounds__(SCAN_BLK)
void scan_partial_kernel(const int* __restrict__ deg,
                         int* __restrict__ rowstart,
                         int* __restrict__ blocksum, int n) {
    __shared__ int sh[SCAN_BLK];
    int t = threadIdx.x;
    int i = blockIdx.x * SCAN_BLK + t;
    int v = (i < n) ? deg[i] : 0;
    sh[t] = v;
    __syncthreads();
    for (int off = 1; off < SCAN_BLK; off <<= 1) {
        int u = (t >= off) ? sh[t - off] : 0;
        __syncthreads();
        sh[t] += u;
        __syncthreads();
    }
    if (i <= n) rowstart[i] = sh[t] - v;   // exclusive
    if (t == SCAN_BLK - 1) blocksum[blockIdx.x] = sh[t];
}

__global__ __launch_bounds__(256)
void scan_blocksums_kernel(int* __restrict__ blocksum, int nb) {
    __shared__ int sh[256];
    int t = threadIdx.x;
    int v = (t < nb) ? blocksum[t] : 0;
    sh[t] = v;
    __syncthreads();
    for (int off = 1; off < 256; off <<= 1) {
        int u = (t >= off) ? sh[t - off] : 0;
        __syncthreads();
        sh[t] += u;
        __syncthreads();
    }
    if (t < nb) blocksum[t] = sh[t] - v;   // exclusive
}

__global__ __launch_bounds__(SCAN_BLK)
void scan_addoff_kernel(int* __restrict__ rowstart,
                        const int* __restrict__ blocksum,
                        int* __restrict__ cursor, int n) {
    int i = blockIdx.x * SCAN_BLK + threadIdx.x;
    if (i > n) return;
    int r = rowstart[i] + blocksum[blockIdx.x];
    rowstart[i] = r;
    if (i < n) cursor[i] = r;
}

// ---------------------------------------------------------------------------
// fill CSR adjacency — 2 edges per thread, 16B index loads
__global__ void fill_kernel(const void* __restrict__ ei,
                            int* __restrict__ cursor,
                            int* __restrict__ csr, int E, int n) {
    int t = blockIdx.x * blockDim.x + threadIdx.x;
    int e = t * 2;
    if (e >= E) return;
    long long s0, s1, d0, d1;
    if (g_ei64) {
        longlong2 sv = *(const longlong2*)((const long long*)ei + e);
        longlong2 dv = *(const longlong2*)((const long long*)ei + E + e);
        s0 = sv.x; s1 = sv.y; d0 = dv.x; d1 = dv.y;
    } else {
        int2 sv = *(const int2*)((const int*)ei + e);
        int2 dv = *(const int2*)((const int*)ei + E + e);
        s0 = sv.x; s1 = sv.y; d0 = dv.x; d1 = dv.y;
    }
    if ((unsigned long long)d0 < (unsigned long long)n) {
        int sc = max(0, min((int)s0, n - 1));
        csr[atomicAdd(cursor + d0, 1)] = sc;
    }
    if (e + 1 < E && (unsigned long long)d1 < (unsigned long long)n) {
        int sc = max(0, min((int)s1, n - 1));
        csr[atomicAdd(cursor + d1, 1)] = sc;
    }
}

// ---------------------------------------------------------------------------
// Per-layer aggregation: warp per node, mean of neighbor rows (no atomics).
// Each lane owns 2 features (float2); up to 16 neighbor rows in flight.
__global__ __launch_bounds__(256)
void aggregate_kernel(const float* __restrict__ x,
                      const int* __restrict__ rowstart,
                      const int* __restrict__ csr,
                      float* __restrict__ agg, int n) {
    int w = (blockIdx.x * blockDim.x + threadIdx.x) >> 5;
    if (w >= n) return;
    int lane = threadIdx.x & 31;
    int beg = rowstart[w], end = rowstart[w + 1];
    const float2* x2 = (const float2*)x;
    float ax = 0.f, ay = 0.f;
    int j = beg;
    for (; j + 16 <= end; j += 16) {
        int idx[16];
#pragma unroll
        for (int u = 0; u < 16; u++) idx[u] = csr[j + u];
        float2 v[16];
#pragma unroll
        for (int u = 0; u < 16; u++) v[u] = x2[(size_t)idx[u] * 32 + lane];
        float sx = 0.f, sy = 0.f;
#pragma unroll
        for (int u = 0; u < 16; u++) { sx += v[u].x; sy += v[u].y; }
        ax += sx; ay += sy;
    }
    for (; j + 4 <= end; j += 4) {
        int i0 = csr[j], i1 = csr[j + 1], i2 = csr[j + 2], i3 = csr[j + 3];
        float2 v0 = x2[(size_t)i0 * 32 + lane];
        float2 v1 = x2[(size_t)i1 * 32 + lane];
        float2 v2 = x2[(size_t)i2 * 32 + lane];
        float2 v3 = x2[(size_t)i3 * 32 + lane];
        ax += (v0.x + v1.x) + (v2.x + v3.x);
        ay += (v0.y + v1.y) + (v2.y + v3.y);
    }
    for (; j < end; j++) {
        int nb = csr[j];
        float2 v = x2[(size_t)nb * 32 + lane];
        ax += v.x; ay += v.y;
    }
    float inv = 1.0f / fmaxf((float)(end - beg), 1.0f);
    ((float2*)agg)[(size_t)w * 32 + lane] = make_float2(ax * inv, ay * inv);
}

// ---------------------------------------------------------------------------
// packed f32x2 FMA (FFMA2 — only reachable via PTX fma.rn.f32x2)
__device__ __forceinline__ unsigned long long fma2(unsigned long long a,
                                                   unsigned long long b,
                                                   unsigned long long c) {
    unsigned long long d;
    asm("fma.rn.f32x2 %0, %1, %2, %3;" : "=l"(d) : "l"(a), "l"(b), "l"(c));
    return d;
}
__device__ __forceinline__ unsigned long long bcast2(float a) {
    unsigned long long r;
    asm("mov.b64 %0, {%1, %1};" : "=l"(r) : "f"(a));
    return r;
}

// Fused layer: out = relu( agg @ Wl^T + bl + x @ Wr^T ),  agg pre-scaled 1/deg.
// Weights arrive PRE-TRANSPOSED ([k][j]) -> prologue is a coalesced float4
// copy with linear, conflict-free STS. One thread per node; 32 packed f32x2
// register accumulators; weight reads are warp-uniform LDS.128 broadcasts.
__global__ __launch_bounds__(256)
void sage_gemm_kernel(const float* __restrict__ x,
                      const float* __restrict__ agg,
                      const float* __restrict__ WlT,
                      const float* __restrict__ bl,
                      const float* __restrict__ WrT,
                      float* __restrict__ out, int n) {
    __shared__ __align__(16) float Wls[FEATS * FEATS];  // [k][j]
    __shared__ __align__(16) float Wrs[FEATS * FEATS];  // [k][j]
    __shared__ __align__(16) float bls[FEATS];

    {
        const float4* sl = (const float4*)WlT;
        const float4* sr = (const float4*)WrT;
        float4* dl = (float4*)Wls;
        float4* dr = (float4*)Wrs;
        for (int i = threadIdx.x; i < (FEATS * FEATS) / 4; i += 256) {
            dl[i] = sl[i];
            dr[i] = sr[i];
        }
        if (threadIdx.x < FEATS / 4)
            ((float4*)bls)[threadIdx.x] = ((const float4*)bl)[threadIdx.x];
    }
    __syncthreads();

    int node = blockIdx.x * blockDim.x + threadIdx.x;
    if (node >= n) return;

    const float4* xr = (const float4*)(x + (size_t)node * FEATS);
    const float4* ar = (const float4*)(agg + (size_t)node * FEATS);

    unsigned long long acc[32];
    const unsigned long long* b2 = (const unsigned long long*)bls;
#pragma unroll
    for (int p = 0; p < 32; p++) acc[p] = b2[p];

    float4 xv = xr[0];
    float4 av = ar[0];
#pragma unroll 1
    for (int kq = 0; kq < 16; kq++) {
        float4 xn, an;
        if (kq < 15) { xn = xr[kq + 1]; an = ar[kq + 1]; }
        float ax[4] = {xv.x, xv.y, xv.z, xv.w};
        float aa[4] = {av.x, av.y, av.z, av.w};
#pragma unroll
        for (int kk = 0; kk < 4; kk++) {
            int k = kq * 4 + kk;
            unsigned long long a2 = bcast2(aa[kk]);
            unsigned long long s2 = bcast2(ax[kk]);
            const ulonglong2* wl2 = (const ulonglong2*)(Wls + (k << 6));
            const ulonglong2* wr2 = (const ulonglong2*)(Wrs + (k << 6));
#pragma unroll
            for (int q = 0; q < 16; q++) {
                ulonglong2 wl = wl2[q];
                ulonglong2 wr = wr2[q];
                acc[2 * q]     = fma2(a2, wl.x, fma2(s2, wr.x, acc[2 * q]));
                acc[2 * q + 1] = fma2(a2, wl.y, fma2(s2, wr.y, acc[2 * q + 1]));
            }
        }
        xv = xn; av = an;
    }

    float4* o = (float4*)(out + (size_t)node * FEATS);
#pragma unroll
    for (int q = 0; q < 16; q++) {
        unsigned long long v0 = acc[2 * q], v1 = acc[2 * q + 1];
        float4 r;
        r.x = fmaxf(__uint_as_float((unsigned)v0),         0.f);
        r.y = fmaxf(__uint_as_float((unsigned)(v0 >> 32)), 0.f);
        r.z = fmaxf(__uint_as_float((unsigned)v1),         0.f);
        r.w = fmaxf(__uint_as_float((unsigned)(v1 >> 32)), 0.f);
        o[q] = r;
    }
}

// ---------------------------------------------------------------------------
extern "C" void kernel_launch(void* const* d_in, const int* in_sizes, int n_in,
                              void* d_out, int out_size) {
    // Identify inputs by element count (robust to metadata ordering):
    //   x: 6,400,000   edge_index: 3,200,000   Wl/Wr: 12,288 (1st/2nd)   bl: 192
    const float* x  = nullptr;
    const void*  ei = nullptr;
    const float* Wl = nullptr;
    const float* Wr = nullptr;
    const float* bl = nullptr;
    for (int i = 0; i < n_in; i++) {
        int s = in_sizes[i];
        if (s == NODES_MAX * FEATS)      x  = (const float*)d_in[i];
        else if (s == 2 * EDGES_MAX)     ei = d_in[i];
        else if (s == 3 * FEATS * FEATS) { if (!Wl) Wl = (const float*)d_in[i]; else Wr = (const float*)d_in[i]; }
        else if (s == 3 * FEATS)         bl = (const float*)d_in[i];
    }
    if (!x || !ei || !Wl || !Wr || !bl) return;

    int n = NODES_MAX;
    int E = EDGES_MAX;

    float *agg, *b0, *b1, *WlT, *WrT;
    int *deg, *rowstart, *cursor, *csr, *bsum;
    cudaGetSymbolAddress((void**)&agg,      g_agg);
    cudaGetSymbolAddress((void**)&b0,       g_buf0);
    cudaGetSymbolAddress((void**)&b1,       g_buf1);
    cudaGetSymbolAddress((void**)&WlT,      g_WlT);
    cudaGetSymbolAddress((void**)&WrT,      g_WrT);
    cudaGetSymbolAddress((void**)&deg,      g_deg);
    cudaGetSymbolAddress((void**)&rowstart, g_rowstart);
    cudaGetSymbolAddress((void**)&cursor,   g_cursor);
    cudaGetSymbolAddress((void**)&csr,      g_csr);
    cudaGetSymbolAddress((void**)&bsum,     g_blocksum);

    const int TB = 256;

    // one-time (per replay): fused setup + CSR build (vectorized edge loads)
    setup_kernel<<<(n + TB - 1) / TB, TB>>>((const unsigned int*)ei, Wl, Wr,
                                            WlT, WrT, deg, n);
    int half = (E + 1) / 2;
    hist_kernel<<<(half + TB - 1) / TB, TB>>>(ei, deg, E, n);
    scan_partial_kernel<<<SCAN_NBLK, SCAN_BLK>>>(deg, rowstart, bsum, n);
    scan_blocksums_kernel<<<1, 256>>>(bsum, SCAN_NBLK);
    scan_addoff_kernel<<<SCAN_NBLK, SCAN_BLK>>>(rowstart, bsum, cursor, n);
    fill_kernel<<<(half + TB - 1) / TB, TB>>>(ei, cursor, csr, E, n);

    const float* cur = x;
    float* outs[3] = { b0, b1, (float*)d_out };
    int agg_blocks = (n * 32 + TB - 1) / TB;  // warp per node, 8 warps/block

    for (int i = 0; i < 3; i++) {
        aggregate_kernel<<<agg_blocks, TB>>>(cur, rowstart, csr, agg, n);
        sage_gemm_kernel<<<(n + 255) / 256, 256>>>(
            cur, agg, WlT + i * 4096, bl + i * 64, WrT + i * 4096, outs[i], n);
        cur = outs[i];
    }
}

// round 14
// speedup vs baseline: 1.5264x; 1.5264x over previous
#include <cuda_runtime.h>
#include <cuda_bf16.h>
#include <cstdint>

// Problem constants: N=100000, E=1600000, D=64, L=3
#define NODES_MAX 100000
#define EDGES_MAX 1600000
#define FEATS     64
#define SCAN_BLK  512
#define SCAN_NBLK ((NODES_MAX + 1 + SCAN_BLK - 1) / SCAN_BLK)   // 196

// Scratch (device globals: runtime allocation forbidden)
__device__ __align__(16) float g_agg [NODES_MAX * FEATS];
__device__ __align__(16) float g_buf0[NODES_MAX * FEATS];
__device__ __align__(16) float g_buf1[NODES_MAX * FEATS];
__device__ __align__(16) float g_WlT [3 * FEATS * FEATS];   // transposed [k][j]
__device__ __align__(16) float g_WrT [3 * FEATS * FEATS];   // transposed [k][j]
__device__ int g_deg     [NODES_MAX];
__device__ int g_rowstart[NODES_MAX + 1];
__device__ int g_cursor  [NODES_MAX];
__device__ int g_csr     [EDGES_MAX];
__device__ int g_blocksum[SCAN_NBLK];
__device__ int g_ei64;   // 1 = edge_index is int64, 0 = int32

// ---------------------------------------------------------------------------
// Fused one-time setup: zero deg, transpose weights, detect edge-index dtype.
// (int64 values < 2^31 => every odd 32-bit word of the buffer is zero.)
__global__ void setup_kernel(const unsigned int* __restrict__ eiw,
                             const float* __restrict__ Wl,
                             const float* __restrict__ Wr,
                             float* __restrict__ WlT,
                             float* __restrict__ WrT,
                             int* __restrict__ deg, int n) {
    int i = blockIdx.x * blockDim.x + threadIdx.x;
    if (i < n) deg[i] = 0;
    if (i < 3 * FEATS * FEATS) {
        int layer = i >> 12, r = i & 4095;
        int j = r >> 6, k = r & 63;
        WlT[(layer << 12) + (k << 6) + j] = Wl[i];
        WrT[(layer << 12) + (k << 6) + j] = Wr[i];
    }
    if (blockIdx.x == 0) {
        __shared__ unsigned int rr;
        if (threadIdx.x == 0) rr = 0u;
        __syncthreads();
        unsigned int v = eiw[2 * threadIdx.x + 1];   // 256 odd words
        atomicOr(&rr, v);
        __syncthreads();
        if (threadIdx.x == 0) g_ei64 = (rr == 0u) ? 1 : 0;
    }
}

__device__ __forceinline__ long long load_idx(const void* ei, long long pos, int is64) {
    if (is64) return ((const long long*)ei)[pos];
    return (long long)((const int*)ei)[pos];
}

// ---------------------------------------------------------------------------
// in-degree histogram (scalar — atomic-throughput-bound, known-good config)
__global__ void hist_kernel(const void* __restrict__ ei, int* __restrict__ deg,
                            int E, int n) {
    int e = blockIdx.x * blockDim.x + threadIdx.x;
    if (e >= E) return;
    long long d = load_idx(ei, (long long)E + e, g_ei64);
    if ((unsigned long long)d < (unsigned long long)n)
        atomicAdd(deg + d, 1);
}

// ---------------------------------------------------------------------------
// Chip-wide exclusive scan, now 2 kernels (blocksum scan folded into addoff).
__global__ __launch_bounds__(SCAN_BLK)
void scan_partial_kernel(const int* __restrict__ deg,
                         int* __restrict__ rowstart,
                         int* __restrict__ blocksum, int n) {
    __shared__ int sh[SCAN_BLK];
    int t = threadIdx.x;
    int i = blockIdx.x * SCAN_BLK + t;
    int v = (i < n) ? deg[i] : 0;
    sh[t] = v;
    __syncthreads();
    for (int off = 1; off < SCAN_BLK; off <<= 1) {
        int u = (t >= off) ? sh[t - off] : 0;
        __syncthreads();
        sh[t] += u;
        __syncthreads();
    }
    if (i <= n) rowstart[i] = sh[t] - v;   // exclusive (local)
    if (t == SCAN_BLK - 1) blocksum[blockIdx.x] = sh[t];  // block total
}

// each block reduces blocksum[0..blockIdx) itself -> no separate scan kernel
__global__ __launch_bounds__(SCAN_BLK)
void scan_addoff_kernel(int* __restrict__ rowstart,
                        const int* __restrict__ blocksum,
                        int* __restrict__ cursor, int n, int nb) {
    __shared__ int sh[SCAN_BLK];
    int t = threadIdx.x;
    sh[t] = (t < blockIdx.x && t < nb) ? blocksum[t] : 0;
    __syncthreads();
    for (int off = SCAN_BLK / 2; off > 0; off >>= 1) {
        if (t < off) sh[t] += sh[t + off];
        __syncthreads();
    }
    int offset = sh[0];

    int i = blockIdx.x * SCAN_BLK + t;
    if (i > n) return;
    int r = rowstart[i] + offset;
    rowstart[i] = r;
    if (i < n) cursor[i] = r;
}

// fill CSR adjacency: csr[atomicAdd(cursor[dst])] = src  (scalar, known-good)
__global__ void fill_kernel(const void* __restrict__ ei,
                            int* __restrict__ cursor,
                            int* __restrict__ csr, int E, int n) {
    int e = blockIdx.x * blockDim.x + threadIdx.x;
    if (e >= E) return;
    int is64 = g_ei64;
    long long s = load_idx(ei, e, is64);
    long long d = load_idx(ei, (long long)E + e, is64);
    if ((unsigned long long)d >= (unsigned long long)n) return;
    int sc = (int)s;
    sc = max(0, min(sc, n - 1));  // clamp: no holes, no OOB
    int pos = atomicAdd(cursor + d, 1);
    csr[pos] = sc;
}

// ---------------------------------------------------------------------------
// Per-layer aggregation: warp per node, mean of neighbor rows (no atomics).
// Each lane owns 2 features (float2); 8 neighbor rows in flight per warp.
// NOTE: 8-deep batching is deliberate — 16-deep trips the cross-CTA
// L1tex-queue spread law (spr_max ~2x at occ8, MLP_p1>=12) and regresses ~50%.
__global__ __launch_bounds__(256)
void aggregate_kernel(const float* __restrict__ x,
                      const int* __restrict__ rowstart,
                      const int* __restrict__ csr,
                      float* __restrict__ agg, int n) {
    int w = (blockIdx.x * blockDim.x + threadIdx.x) >> 5;
    if (w >= n) return;
    int lane = threadIdx.x & 31;
    int beg = rowstart[w], end = rowstart[w + 1];
    const float2* x2 = (const float2*)x;
    float ax = 0.f, ay = 0.f;
    int j = beg;
    for (; j + 8 <= end; j += 8) {
        int i0 = csr[j],     i1 = csr[j + 1], i2 = csr[j + 2], i3 = csr[j + 3];
        int i4 = csr[j + 4], i5 = csr[j + 5], i6 = csr[j + 6], i7 = csr[j + 7];
        float2 v0 = x2[(size_t)i0 * 32 + lane];
        float2 v1 = x2[(size_t)i1 * 32 + lane];
        float2 v2 = x2[(size_t)i2 * 32 + lane];
        float2 v3 = x2[(size_t)i3 * 32 + lane];
        float2 v4 = x2[(size_t)i4 * 32 + lane];
        float2 v5 = x2[(size_t)i5 * 32 + lane];
        float2 v6 = x2[(size_t)i6 * 32 + lane];
        float2 v7 = x2[(size_t)i7 * 32 + lane];
        ax += ((v0.x + v1.x) + (v2.x + v3.x)) + ((v4.x + v5.x) + (v6.x + v7.x));
        ay += ((v0.y + v1.y) + (v2.y + v3.y)) + ((v4.y + v5.y) + (v6.y + v7.y));
    }
    for (; j < end; j++) {
        int nb = csr[j];
        float2 v = x2[(size_t)nb * 32 + lane];
        ax += v.x; ay += v.y;
    }
    float inv = 1.0f / fmaxf((float)(end - beg), 1.0f);
    ((float2*)agg)[(size_t)w * 32 + lane] = make_float2(ax * inv, ay * inv);
}

// ---------------------------------------------------------------------------
// packed f32x2 FMA (FFMA2 — only reachable via PTX fma.rn.f32x2)
__device__ __forceinline__ unsigned long long fma2(unsigned long long a,
                                                   unsigned long long b,
                                                   unsigned long long c) {
    unsigned long long d;
    asm("fma.rn.f32x2 %0, %1, %2, %3;" : "=l"(d) : "l"(a), "l"(b), "l"(c));
    return d;
}
__device__ __forceinline__ unsigned long long bcast2(float a) {
    unsigned long long r;
    asm("mov.b64 %0, {%1, %1};" : "=l"(r) : "f"(a));
    return r;
}

// Fused layer: out = relu( agg @ Wl^T + bl + x @ Wr^T ),  agg pre-scaled 1/deg.
// Weights arrive PRE-TRANSPOSED ([k][j]) -> prologue is a coalesced float4
// copy with linear, conflict-free STS. One thread per node; 32 packed f32x2
// register accumulators; weight reads are warp-uniform LDS.128 broadcasts.
__global__ __launch_bounds__(256)
void sage_gemm_kernel(const float* __restrict__ x,
                      const float* __restrict__ agg,
                      const float* __restrict__ WlT,
                      const float* __restrict__ bl,
                      const float* __restrict__ WrT,
                      float* __restrict__ out, int n) {
    __shared__ __align__(16) float Wls[FEATS * FEATS];  // [k][j]
    __shared__ __align__(16) float Wrs[FEATS * FEATS];  // [k][j]
    __shared__ __align__(16) float bls[FEATS];

    {
        const float4* sl = (const float4*)WlT;
        const float4* sr = (const float4*)WrT;
        float4* dl = (float4*)Wls;
        float4* dr = (float4*)Wrs;
        for (int i = threadIdx.x; i < (FEATS * FEATS) / 4; i += 256) {
            dl[i] = sl[i];
            dr[i] = sr[i];
        }
        if (threadIdx.x < FEATS / 4)
            ((float4*)bls)[threadIdx.x] = ((const float4*)bl)[threadIdx.x];
    }
    __syncthreads();

    int node = blockIdx.x * blockDim.x + threadIdx.x;
    if (node >= n) return;

    const float4* xr = (const float4*)(x + (size_t)node * FEATS);
    const float4* ar = (const float4*)(agg + (size_t)node * FEATS);

    unsigned long long acc[32];
    const unsigned long long* b2 = (const unsigned long long*)bls;
#pragma unroll
    for (int p = 0; p < 32; p++) acc[p] = b2[p];

    float4 xv = xr[0];
    float4 av = ar[0];
#pragma unroll 1
    for (int kq = 0; kq < 16; kq++) {
        float4 xn, an;
        if (kq < 15) { xn = xr[kq + 1]; an = ar[kq + 1]; }
        float ax[4] = {xv.x, xv.y, xv.z, xv.w};
        float aa[4] = {av.x, av.y, av.z, av.w};
#pragma unroll
        for (int kk = 0; kk < 4; kk++) {
            int k = kq * 4 + kk;
            unsigned long long a2 = bcast2(aa[kk]);
            unsigned long long s2 = bcast2(ax[kk]);
            const ulonglong2* wl2 = (const ulonglong2*)(Wls + (k << 6));
            const ulonglong2* wr2 = (const ulonglong2*)(Wrs + (k << 6));
#pragma unroll
            for (int q = 0; q < 16; q++) {
                ulonglong2 wl = wl2[q];
                ulonglong2 wr = wr2[q];
                acc[2 * q]     = fma2(a2, wl.x, fma2(s2, wr.x, acc[2 * q]));
                acc[2 * q + 1] = fma2(a2, wl.y, fma2(s2, wr.y, acc[2 * q + 1]));
            }
        }
        xv = xn; av = an;
    }

    float4* o = (float4*)(out + (size_t)node * FEATS);
#pragma unroll
    for (int q = 0; q < 16; q++) {
        unsigned long long v0 = acc[2 * q], v1 = acc[2 * q + 1];
        float4 r;
        r.x = fmaxf(__uint_as_float((unsigned)v0),         0.f);
        r.y = fmaxf(__uint_as_float((unsigned)(v0 >> 32)), 0.f);
        r.z = fmaxf(__uint_as_float((unsigned)v1),         0.f);
        r.w = fmaxf(__uint_as_float((unsigned)(v1 >> 32)), 0.f);
        o[q] = r;
    }
}

// ---------------------------------------------------------------------------
extern "C" void kernel_launch(void* const* d_in, const int* in_sizes, int n_in,
                              void* d_out, int out_size) {
    // Identify inputs by element count (robust to metadata ordering):
    //   x: 6,400,000   edge_index: 3,200,000   Wl/Wr: 12,288 (1st/2nd)   bl: 192
    const float* x  = nullptr;
    const void*  ei = nullptr;
    const float* Wl = nullptr;
    const float* Wr = nullptr;
    const float* bl = nullptr;
    for (int i = 0; i < n_in; i++) {
        int s = in_sizes[i];
        if (s == NODES_MAX * FEATS)      x  = (const float*)d_in[i];
        else if (s == 2 * EDGES_MAX)     ei = d_in[i];
        else if (s == 3 * FEATS * FEATS) { if (!Wl) Wl = (const float*)d_in[i]; else Wr = (const float*)d_in[i]; }
        else if (s == 3 * FEATS)         bl = (const float*)d_in[i];
    }
    if (!x || !ei || !Wl || !Wr || !bl) return;

    int n = NODES_MAX;
    int E = EDGES_MAX;

    float *agg, *b0, *b1, *WlT, *WrT;
    int *deg, *rowstart, *cursor, *csr, *bsum;
    cudaGetSymbolAddress((void**)&agg,      g_agg);
    cudaGetSymbolAddress((void**)&b0,       g_buf0);
    cudaGetSymbolAddress((void**)&b1,       g_buf1);
    cudaGetSymbolAddress((void**)&WlT,      g_WlT);
    cudaGetSymbolAddress((void**)&WrT,      g_WrT);
    cudaGetSymbolAddress((void**)&deg,      g_deg);
    cudaGetSymbolAddress((void**)&rowstart, g_rowstart);
    cudaGetSymbolAddress((void**)&cursor,   g_cursor);
    cudaGetSymbolAddress((void**)&csr,      g_csr);
    cudaGetSymbolAddress((void**)&bsum,     g_blocksum);

    const int TB = 256;

    // one-time (per replay): fused setup + CSR build (11 launches total)
    setup_kernel<<<(n + TB - 1) / TB, TB>>>((const unsigned int*)ei, Wl, Wr,
                                            WlT, WrT, deg, n);
    hist_kernel<<<(E + TB - 1) / TB, TB>>>(ei, deg, E, n);
    scan_partial_kernel<<<SCAN_NBLK, SCAN_BLK>>>(deg, rowstart, bsum, n);
    scan_addoff_kernel<<<SCAN_NBLK, SCAN_BLK>>>(rowstart, bsum, cursor, n, SCAN_NBLK);
    fill_kernel<<<(E + TB - 1) / TB, TB>>>(ei, cursor, csr, E, n);

    const float* cur = x;
    float* outs[3] = { b0, b1, (float*)d_out };
    int agg_blocks = (n * 32 + TB - 1) / TB;  // warp per node, 8 warps/block

    for (int i = 0; i < 3; i++) {
        aggregate_kernel<<<agg_blocks, TB>>>(cur, rowstart, csr, agg, n);
        sage_gemm_kernel<<<(n + 255) / 256, 256>>>(
            cur, agg, WlT + i * 4096, bl + i * 64, WrT + i * 4096, outs[i], n);
        cur = outs[i];
    }
}